// round 8
// baseline (speedup 1.0000x reference)
#include <cuda_runtime.h>
#include <cuda_fp16.h>
#include <cstdint>

// ---------------- problem constants ----------------
#define KCL      1024
#define DIM      128
#define BROWS    262144
#define M_CTA    256              // rows per CTA (pass 1)
#define NCHUNK_P 128              // protos per chunk
#define NCHUNKS  8                // 1024/128
#define BROW_B   272              // padded bytes per proto row -> LDSM conflict-free
#define HI_BLK   (NCHUNK_P * BROW_B)        // 34816 bytes per hi chunk
#define HI_CP    (HI_BLK / 16)              // 2176 cp.async ops per chunk
// hi-pass error bound: delta <= 9.9e-4*||e||.  2*delta = 1.97e-3.
#define C2_CERT  2.5e-3f          // v1-v2 certification (27% margin)
#define C3_LISTA 2.3e-3f          // v1-v4 top-3-candidate certification (17% margin)

#define P1_SMEM  (2 * HI_BLK + 1024)        // hi double buffer + rowBest[256]

typedef uint32_t u32;

// ---------------- device scratch (no allocs) ----------------
__device__ __align__(16) char  g_Bimg[NCHUNKS * HI_BLK];  // hi fp16 proto image (padded)
__device__ __align__(16) float g_proto_n[KCL * DIM];      // fp32 normalized protos
__device__ __align__(16) float g_sums[KCL * DIM];
__device__ float g_counts[KCL];
__device__ int4  g_listA[BROWS];   // (row, i1, i2, i3)
__device__ int   g_listB[BROWS];   // rows needing full exact scan
__device__ int   g_nA, g_nB;

// ---------------- PTX helpers (plain-sm_100-legal) ----------------
__device__ __forceinline__ u32 smem_u32(const void* p) {
    u32 a;
    asm("{ .reg .u64 t; cvta.to.shared.u64 t, %1; cvt.u32.u64 %0, t; }" : "=r"(a) : "l"(p));
    return a;
}
__device__ __forceinline__ void cp16(u32 dst, const void* src) {
    asm volatile("cp.async.cg.shared.global [%0], [%1], 16;" :: "r"(dst), "l"(src) : "memory");
}
__device__ __forceinline__ void cp_commit() { asm volatile("cp.async.commit_group;" ::: "memory"); }
__device__ __forceinline__ void cp_wait0()  { asm volatile("cp.async.wait_group 0;" ::: "memory"); }

__device__ __forceinline__ void ldsm4(u32* r, u32 addr) {
    asm volatile("ldmatrix.sync.aligned.m8n8.x4.shared.b16 {%0,%1,%2,%3}, [%4];"
                 : "=r"(r[0]), "=r"(r[1]), "=r"(r[2]), "=r"(r[3]) : "r"(addr));
}
__device__ __forceinline__ void mma16(float* d, const u32* a, const u32* b) {
    asm volatile(
        "mma.sync.aligned.m16n8k16.row.col.f32.f16.f16.f32 "
        "{%0,%1,%2,%3}, {%4,%5,%6,%7}, {%8,%9}, {%0,%1,%2,%3};"
        : "+f"(d[0]), "+f"(d[1]), "+f"(d[2]), "+f"(d[3])
        : "r"(a[0]), "r"(a[1]), "r"(a[2]), "r"(a[3]), "r"(b[0]), "r"(b[1]));
}
__device__ __forceinline__ void red4(float* gp, float4 v) {
    asm volatile("red.global.add.v4.f32 [%0], {%1,%2,%3,%4};"
                 :: "l"(gp), "f"(v.x), "f"(v.y), "f"(v.z), "f"(v.w) : "memory");
}
__device__ __forceinline__ u32 hi2(float2 v) {
    __half2 h2 = __halves2half2(__float2half_rn(v.x), __float2half_rn(v.y));
    return *(u32*)&h2;
}
// top-4 insert (values) with top-3 indices
__device__ __forceinline__ void fold4(float x, int c,
    float& v1, int& i1, float& v2, int& i2, float& v3, int& i3, float& v4) {
    if (x > v1)      { v4 = v3; v3 = v2; i3 = i2; v2 = v1; i2 = i1; v1 = x; i1 = c; }
    else if (x > v2) { v4 = v3; v3 = v2; i3 = i2; v2 = x; i2 = c; }
    else if (x > v3) { v4 = v3; v3 = x; i3 = c; }
    else if (x > v4) { v4 = x; }
}

// ---------------------------------------------------------------------------
// Prep: normalize prototypes (x / max(||x||, eps)) -> g_proto_n (fp32) and
// hi-fp16 padded image for pass-1. Zero sums/counts/list counters.
__global__ void prep_kernel(const float* __restrict__ proto) {
    int k = blockIdx.x, t = threadIdx.x;
    float v = proto[k * DIM + t];
    float s = v * v;
    #pragma unroll
    for (int m = 16; m; m >>= 1) s += __shfl_xor_sync(0xffffffffu, s, m);
    __shared__ float ws[4];
    if ((t & 31) == 0) ws[t >> 5] = s;
    __syncthreads();
    float pn = v * (1.0f / fmaxf(sqrtf(ws[0] + ws[1] + ws[2] + ws[3]), 1e-12f));

    g_proto_n[k * DIM + t] = pn;
    int chunk = k >> 7, n = k & 127;
    *(__half*)(g_Bimg + (size_t)chunk * HI_BLK + n * BROW_B + t * 2) = __float2half_rn(pn);

    g_sums[k * DIM + t] = 0.0f;
    if (t == 0) g_counts[k] = 0.0f;
    if (k == 0 && t == 0) { g_nA = 0; g_nB = 0; }
}

// ---------------------------------------------------------------------------
// Pass 1: hi-fp16 GEMM, per-row top-4 (values) + top-3 (indices).
// Certified rows scatter immediately; others go to listA (3 exact candidates)
// or listB (full exact scan).
__global__ void __launch_bounds__(256, 2)
pass1_kernel(const float* __restrict__ emb) {
    extern __shared__ char dsm[];
    const u32 sbase = smem_u32(dsm);
    int* rowBest = (int*)(dsm + 2 * HI_BLK);

    const int tid  = threadIdx.x;
    const int wid  = tid >> 5;
    const int lane = tid & 31;
    const int g    = lane >> 2;
    const int qi   = lane & 3;
    const int rowBase = blockIdx.x * M_CTA;
    const float* ebase = emb + (size_t)rowBase * DIM;

    // ---- A hi fragments + row norms ----
    u32 AHI[2][8][4];
    float nrm2[4] = {0.f, 0.f, 0.f, 0.f};
    #pragma unroll
    for (int t2 = 0; t2 < 2; ++t2) {
        const int rA = t2 * 128 + wid * 16 + g;
        #pragma unroll
        for (int ks = 0; ks < 8; ++ks) {
            const int c0 = ks * 16 + 2 * qi;
            float2 v0 = *(const float2*)(ebase + (size_t)rA * DIM + c0);
            float2 v1 = *(const float2*)(ebase + (size_t)(rA + 8) * DIM + c0);
            float2 v2 = *(const float2*)(ebase + (size_t)rA * DIM + c0 + 8);
            float2 v3 = *(const float2*)(ebase + (size_t)(rA + 8) * DIM + c0 + 8);
            AHI[t2][ks][0] = hi2(v0); AHI[t2][ks][1] = hi2(v1);
            AHI[t2][ks][2] = hi2(v2); AHI[t2][ks][3] = hi2(v3);
            nrm2[t2 * 2]     += v0.x * v0.x + v0.y * v0.y + v2.x * v2.x + v2.y * v2.y;
            nrm2[t2 * 2 + 1] += v1.x * v1.x + v1.y * v1.y + v3.x * v3.x + v3.y * v3.y;
        }
    }
    #pragma unroll
    for (int m = 1; m <= 2; m <<= 1)
        #pragma unroll
        for (int q = 0; q < 4; ++q)
            nrm2[q] += __shfl_xor_sync(0xffffffffu, nrm2[q], m);

    const u32 laneOff = (u32)((lane & 7) * BROW_B + (lane >> 3) * 16);

    // stage chunk 0
    #pragma unroll
    for (int j = 0; j < 9; ++j) {
        int idx = j * 256 + tid;
        if (idx < HI_CP) cp16(sbase + idx * 16, g_Bimg + idx * 16);
    }
    cp_commit(); cp_wait0();
    __syncthreads();

    float V1[4], V2[4], V3[4], V4[4];
    int   I1[4], I2[4], I3[4];
    #pragma unroll
    for (int q = 0; q < 4; ++q) {
        V1[q] = V2[q] = V3[q] = V4[q] = -3.4e38f;
        I1[q] = I2[q] = I3[q] = 0;
    }

    for (int c = 0; c < NCHUNKS; ++c) {
        const u32 bb = sbase + (u32)(c & 1) * HI_BLK;
        if (c < NCHUNKS - 1) {
            const char* src = g_Bimg + (size_t)(c + 1) * HI_BLK;
            const u32 nb = sbase + (u32)((c + 1) & 1) * HI_BLK;
            #pragma unroll
            for (int j = 0; j < 9; ++j) {
                int idx = j * 256 + tid;
                if (idx < HI_CP) cp16(nb + idx * 16, src + idx * 16);
            }
            cp_commit();
        }

        #pragma unroll 1
        for (int nt = 0; nt < 16; ++nt) {
            float d0[4] = {0.f, 0.f, 0.f, 0.f};
            float d1[4] = {0.f, 0.f, 0.f, 0.f};
            u32 B[8];
            const u32 ntOff = bb + (u32)nt * (8 * BROW_B) + laneOff;
            ldsm4(B, ntOff); ldsm4(B + 4, ntOff + 64);
            #pragma unroll
            for (int ks = 0; ks < 4; ++ks) {
                mma16(d0, AHI[0][ks], &B[2 * ks]);
                mma16(d1, AHI[1][ks], &B[2 * ks]);
            }
            ldsm4(B, ntOff + 128); ldsm4(B + 4, ntOff + 192);
            #pragma unroll
            for (int ks = 4; ks < 8; ++ks) {
                mma16(d0, AHI[0][ks], &B[2 * (ks - 4)]);
                mma16(d1, AHI[1][ks], &B[2 * (ks - 4)]);
            }
            const int c0 = c * NCHUNK_P + nt * 8 + 2 * qi;
            #pragma unroll
            for (int q = 0; q < 4; ++q) {
                const float da = (q < 2) ? d0[q * 2] : d1[(q - 2) * 2];
                const float db = (q < 2) ? d0[q * 2 + 1] : d1[(q - 2) * 2 + 1];
                fold4(da, c0,     V1[q], I1[q], V2[q], I2[q], V3[q], I3[q], V4[q]);
                fold4(db, c0 + 1, V1[q], I1[q], V2[q], I2[q], V3[q], I3[q], V4[q]);
            }
        }
        if (c < NCHUNKS - 1) cp_wait0();
        __syncthreads();
    }

    // ---- quad merge of top-4 lists (union top-3 index always known) ----
    #pragma unroll
    for (int m = 1; m <= 2; m <<= 1) {
        #pragma unroll
        for (int q = 0; q < 4; ++q) {
            float ov1 = __shfl_xor_sync(0xffffffffu, V1[q], m);
            int   oi1 = __shfl_xor_sync(0xffffffffu, I1[q], m);
            float ov2 = __shfl_xor_sync(0xffffffffu, V2[q], m);
            int   oi2 = __shfl_xor_sync(0xffffffffu, I2[q], m);
            float ov3 = __shfl_xor_sync(0xffffffffu, V3[q], m);
            int   oi3 = __shfl_xor_sync(0xffffffffu, I3[q], m);
            float ov4 = __shfl_xor_sync(0xffffffffu, V4[q], m);
            fold4(ov1, oi1, V1[q], I1[q], V2[q], I2[q], V3[q], I3[q], V4[q]);
            fold4(ov2, oi2, V1[q], I1[q], V2[q], I2[q], V3[q], I3[q], V4[q]);
            fold4(ov3, oi3, V1[q], I1[q], V2[q], I2[q], V3[q], I3[q], V4[q]);
            V4[q] = fmaxf(V4[q], ov4);   // ov4 can only land in slot 4
        }
    }

    if (qi == 0) {
        #pragma unroll
        for (int q = 0; q < 4; ++q) {
            const int rl = (q >> 1) * 128 + wid * 16 + (q & 1) * 8 + g;
            const float nrm = sqrtf(nrm2[q]);
            if (V1[q] - V2[q] > C2_CERT * nrm) {
                rowBest[rl] = I1[q];
            } else {
                rowBest[rl] = -1;
                if (V1[q] - V4[q] > C3_LISTA * nrm) {
                    int pos = atomicAdd(&g_nA, 1);
                    g_listA[pos] = make_int4(rowBase + rl, I1[q], I2[q], I3[q]);
                } else {
                    int pos = atomicAdd(&g_nB, 1);
                    g_listB[pos] = rowBase + rl;
                }
            }
        }
    }
    __syncthreads();

    // ---- scatter certified rows ----
    {
        int rb = rowBest[tid];
        if (rb >= 0) atomicAdd(&g_counts[rb], 1.0f);
    }
    const float4* e4 = (const float4*)ebase;
    #pragma unroll 4
    for (int it = 0; it < 32; ++it) {
        int idx = it * 256 + tid;
        int r  = idx >> 5;
        int c4 = idx & 31;
        int rb = rowBest[r];
        if (rb >= 0) red4(&g_sums[rb * DIM + c4 * 4], e4[r * 32 + c4]);
    }
}

// ---------------------------------------------------------------------------
// Refine: warp-per-row. listA rows -> 3 exact fp32 dots among certified
// candidates; listB rows -> full exact fp32 scan over all K. Then scatter.
__global__ void __launch_bounds__(256, 2)
refine_kernel(const float* __restrict__ emb) {
    const int w    = blockIdx.x * 8 + (threadIdx.x >> 5);
    const int lane = threadIdx.x & 31;
    const int W    = gridDim.x * 8;
    const int nA = *(volatile int*)&g_nA;
    const int nB = *(volatile int*)&g_nB;
    const float4* p4 = (const float4*)g_proto_n;

    for (int i = w; i < nA; i += W) {
        int4 ent = g_listA[i];
        const float4 ef = ((const float4*)(emb + (size_t)ent.x * DIM))[lane];
        float4 pa = p4[ent.y * 32 + lane];
        float4 pb = p4[ent.z * 32 + lane];
        float4 pc = p4[ent.w * 32 + lane];
        float d1 = fmaf(ef.x, pa.x, fmaf(ef.y, pa.y, fmaf(ef.z, pa.z, ef.w * pa.w)));
        float d2 = fmaf(ef.x, pb.x, fmaf(ef.y, pb.y, fmaf(ef.z, pb.z, ef.w * pb.w)));
        float d3 = fmaf(ef.x, pc.x, fmaf(ef.y, pc.y, fmaf(ef.z, pc.z, ef.w * pc.w)));
        #pragma unroll
        for (int m = 16; m; m >>= 1) {
            d1 += __shfl_xor_sync(0xffffffffu, d1, m);
            d2 += __shfl_xor_sync(0xffffffffu, d2, m);
            d3 += __shfl_xor_sync(0xffffffffu, d3, m);
        }
        float bv = d1; int bi = ent.y;
        if (d2 > bv || (d2 == bv && ent.z < bi)) { bv = d2; bi = ent.z; }
        if (d3 > bv || (d3 == bv && ent.w < bi)) { bv = d3; bi = ent.w; }
        if (lane == 0) atomicAdd(&g_counts[bi], 1.0f);
        red4(&g_sums[bi * DIM + lane * 4], ef);
    }

    for (int i = w; i < nB; i += W) {
        int row = g_listB[i];
        const float4 ef = ((const float4*)(emb + (size_t)row * DIM))[lane];
        float bv = -3.4e38f; int bi = 0;
        for (int k = 0; k < KCL; ++k) {
            float4 pf = p4[k * 32 + lane];
            float d = fmaf(ef.x, pf.x, fmaf(ef.y, pf.y, fmaf(ef.z, pf.z, ef.w * pf.w)));
            #pragma unroll
            for (int m = 16; m; m >>= 1) d += __shfl_xor_sync(0xffffffffu, d, m);
            if (d > bv) { bv = d; bi = k; }   // ascending k + strict > = first-max
        }
        if (lane == 0) atomicAdd(&g_counts[bi], 1.0f);
        red4(&g_sums[bi * DIM + lane * 4], ef);
    }
}

// ---------------------------------------------------------------------------
__global__ void finalize_kernel(const float* __restrict__ proto,
                                float* __restrict__ out) {
    int i = blockIdx.x * blockDim.x + threadIdx.x;
    int k = i >> 7;
    float c = g_counts[k];
    float p = proto[i];
    float m = g_sums[i] / fmaxf(c, 1.0f);
    out[i] = (c > 0.0f) ? (0.9f * p + 0.1f * m) : p;
}

// ---------------------------------------------------------------------------
extern "C" void kernel_launch(void* const* d_in, const int* in_sizes, int n_in,
                              void* d_out, int out_size) {
    const float* emb   = (const float*)d_in[0];
    const float* proto = (const float*)d_in[1];
    float* out = (float*)d_out;

    cudaFuncSetAttribute(pass1_kernel,
                         cudaFuncAttributeMaxDynamicSharedMemorySize, P1_SMEM);

    prep_kernel<<<KCL, DIM>>>(proto);
    pass1_kernel<<<BROWS / M_CTA, 256, P1_SMEM>>>(emb);
    refine_kernel<<<296, 256>>>(emb);
    finalize_kernel<<<(KCL * DIM) / 256, 256>>>(proto, out);
}

// round 9
// speedup vs baseline: 1.2452x; 1.2452x over previous
#include <cuda_runtime.h>
#include <cuda_fp16.h>
#include <cstdint>

// ---------------- problem constants ----------------
#define KCL      1024
#define DIM      128
#define BROWS    262144
#define M_CTA    256              // rows per CTA (pass 1)
#define NCHUNK_P 128              // protos per chunk
#define NCHUNKS  8                // 1024/128
#define BROW_B   272              // padded bytes per proto row -> LDSM conflict-free
#define HI_BLK   (NCHUNK_P * BROW_B)        // 34816 bytes per hi chunk
#define HI_CP    (HI_BLK / 16)              // 2176 cp.async ops per chunk
// hi-pass worst-case error: delta <= 9.9e-4*||e||; 2*delta = 1.97e-3
#define C2_CERT  2.3e-3f          // pass-1 v1-v2 certification (17% margin)
#define C4_CERT  2.3e-3f          // refineA v1-v4 top-3-candidate certification

#define P1_SMEM  (2 * HI_BLK + 1024)        // hi double buffer + rowBest[256]
#define RA_SMEM  (2 * HI_BLK + 1024)        // hi double buffer + rowIdx[128]

typedef uint32_t u32;

// ---------------- device scratch (no allocs) ----------------
__device__ __align__(16) char  g_Bimg[NCHUNKS * HI_BLK];  // hi fp16 proto image (padded)
__device__ __align__(16) float g_proto_n[KCL * DIM];      // fp32 normalized protos
__device__ __align__(16) float g_sums[KCL * DIM];
__device__ float g_counts[KCL];
__device__ int   g_flag[BROWS];    // rows uncertified by pass-1
__device__ int4  g_listA[BROWS];   // (row, i1, i2, i3) exact-candidate rows
__device__ int   g_listB[BROWS];   // rows needing full exact scan
__device__ int   g_nF, g_nA, g_nB;

// ---------------- PTX helpers (plain-sm_100-legal) ----------------
__device__ __forceinline__ u32 smem_u32(const void* p) {
    u32 a;
    asm("{ .reg .u64 t; cvta.to.shared.u64 t, %1; cvt.u32.u64 %0, t; }" : "=r"(a) : "l"(p));
    return a;
}
__device__ __forceinline__ void cp16(u32 dst, const void* src) {
    asm volatile("cp.async.cg.shared.global [%0], [%1], 16;" :: "r"(dst), "l"(src) : "memory");
}
__device__ __forceinline__ void cp_commit() { asm volatile("cp.async.commit_group;" ::: "memory"); }
__device__ __forceinline__ void cp_wait0()  { asm volatile("cp.async.wait_group 0;" ::: "memory"); }

__device__ __forceinline__ void ldsm4(u32* r, u32 addr) {
    asm volatile("ldmatrix.sync.aligned.m8n8.x4.shared.b16 {%0,%1,%2,%3}, [%4];"
                 : "=r"(r[0]), "=r"(r[1]), "=r"(r[2]), "=r"(r[3]) : "r"(addr));
}
__device__ __forceinline__ void mma16(float* d, const u32* a, const u32* b) {
    asm volatile(
        "mma.sync.aligned.m16n8k16.row.col.f32.f16.f16.f32 "
        "{%0,%1,%2,%3}, {%4,%5,%6,%7}, {%8,%9}, {%0,%1,%2,%3};"
        : "+f"(d[0]), "+f"(d[1]), "+f"(d[2]), "+f"(d[3])
        : "r"(a[0]), "r"(a[1]), "r"(a[2]), "r"(a[3]), "r"(b[0]), "r"(b[1]));
}
__device__ __forceinline__ void red4(float* gp, float4 v) {
    asm volatile("red.global.add.v4.f32 [%0], {%1,%2,%3,%4};"
                 :: "l"(gp), "f"(v.x), "f"(v.y), "f"(v.z), "f"(v.w) : "memory");
}
__device__ __forceinline__ u32 hi2(float2 v) {
    __half2 h2 = __halves2half2(__float2half_rn(v.x), __float2half_rn(v.y));
    return *(u32*)&h2;
}
// top-4 insert (values) with top-3 indices (used only in refineA, 6% of rows)
__device__ __forceinline__ void fold4(float x, int c,
    float& v1, int& i1, float& v2, int& i2, float& v3, int& i3, float& v4) {
    if (x > v1)      { v4 = v3; v3 = v2; i3 = i2; v2 = v1; i2 = i1; v1 = x; i1 = c; }
    else if (x > v2) { v4 = v3; v3 = v2; i3 = i2; v2 = x; i2 = c; }
    else if (x > v3) { v4 = v3; v3 = x; i3 = c; }
    else if (x > v4) { v4 = x; }
}

// ---------------------------------------------------------------------------
// Prep: normalize prototypes (x / max(||x||, eps)) -> g_proto_n (fp32) and
// hi-fp16 padded image for GEMM passes. Zero sums/counts/list counters.
__global__ void prep_kernel(const float* __restrict__ proto) {
    int k = blockIdx.x, t = threadIdx.x;
    float v = proto[k * DIM + t];
    float s = v * v;
    #pragma unroll
    for (int m = 16; m; m >>= 1) s += __shfl_xor_sync(0xffffffffu, s, m);
    __shared__ float ws[4];
    if ((t & 31) == 0) ws[t >> 5] = s;
    __syncthreads();
    float pn = v * (1.0f / fmaxf(sqrtf(ws[0] + ws[1] + ws[2] + ws[3]), 1e-12f));

    g_proto_n[k * DIM + t] = pn;
    int chunk = k >> 7, n = k & 127;
    *(__half*)(g_Bimg + (size_t)chunk * HI_BLK + n * BROW_B + t * 2) = __float2half_rn(pn);

    g_sums[k * DIM + t] = 0.0f;
    if (t == 0) g_counts[k] = 0.0f;
    if (k == 0 && t == 0) { g_nF = 0; g_nA = 0; g_nB = 0; }
}

// ---------------------------------------------------------------------------
// Pass 1: hi-fp16 GEMM with CHEAP top-2 tracking (R7-proven inner loop).
// Certified rows scatter immediately; uncertified rows -> g_flag.
__global__ void __launch_bounds__(256, 2)
pass1_kernel(const float* __restrict__ emb) {
    extern __shared__ char dsm[];
    const u32 sbase = smem_u32(dsm);
    int* rowBest = (int*)(dsm + 2 * HI_BLK);

    const int tid  = threadIdx.x;
    const int wid  = tid >> 5;
    const int lane = tid & 31;
    const int g    = lane >> 2;
    const int qi   = lane & 3;
    const int rowBase = blockIdx.x * M_CTA;
    const float* ebase = emb + (size_t)rowBase * DIM;

    // ---- A hi fragments + row norms ----
    u32 AHI[2][8][4];
    float nrm2[4] = {0.f, 0.f, 0.f, 0.f};
    #pragma unroll
    for (int t2 = 0; t2 < 2; ++t2) {
        const int rA = t2 * 128 + wid * 16 + g;
        #pragma unroll
        for (int ks = 0; ks < 8; ++ks) {
            const int c0 = ks * 16 + 2 * qi;
            float2 v0 = *(const float2*)(ebase + (size_t)rA * DIM + c0);
            float2 v1 = *(const float2*)(ebase + (size_t)(rA + 8) * DIM + c0);
            float2 v2 = *(const float2*)(ebase + (size_t)rA * DIM + c0 + 8);
            float2 v3 = *(const float2*)(ebase + (size_t)(rA + 8) * DIM + c0 + 8);
            AHI[t2][ks][0] = hi2(v0); AHI[t2][ks][1] = hi2(v1);
            AHI[t2][ks][2] = hi2(v2); AHI[t2][ks][3] = hi2(v3);
            nrm2[t2 * 2]     += v0.x * v0.x + v0.y * v0.y + v2.x * v2.x + v2.y * v2.y;
            nrm2[t2 * 2 + 1] += v1.x * v1.x + v1.y * v1.y + v3.x * v3.x + v3.y * v3.y;
        }
    }
    #pragma unroll
    for (int m = 1; m <= 2; m <<= 1)
        #pragma unroll
        for (int q = 0; q < 4; ++q)
            nrm2[q] += __shfl_xor_sync(0xffffffffu, nrm2[q], m);

    const u32 laneOff = (u32)((lane & 7) * BROW_B + (lane >> 3) * 16);

    // stage chunk 0
    #pragma unroll
    for (int j = 0; j < 9; ++j) {
        int idx = j * 256 + tid;
        if (idx < HI_CP) cp16(sbase + idx * 16, g_Bimg + idx * 16);
    }
    cp_commit(); cp_wait0();
    __syncthreads();

    float v1a[4], v2a[4]; int i1a[4];
    #pragma unroll
    for (int q = 0; q < 4; ++q) { v1a[q] = -3.4e38f; v2a[q] = -3.4e38f; i1a[q] = 0; }

    for (int c = 0; c < NCHUNKS; ++c) {
        const u32 bb = sbase + (u32)(c & 1) * HI_BLK;
        if (c < NCHUNKS - 1) {
            const char* src = g_Bimg + (size_t)(c + 1) * HI_BLK;
            const u32 nb = sbase + (u32)((c + 1) & 1) * HI_BLK;
            #pragma unroll
            for (int j = 0; j < 9; ++j) {
                int idx = j * 256 + tid;
                if (idx < HI_CP) cp16(nb + idx * 16, src + idx * 16);
            }
            cp_commit();
        }

        #pragma unroll 1
        for (int nt = 0; nt < 16; ++nt) {
            float d0[4] = {0.f, 0.f, 0.f, 0.f};
            float d1[4] = {0.f, 0.f, 0.f, 0.f};
            u32 B[8];
            const u32 ntOff = bb + (u32)nt * (8 * BROW_B) + laneOff;
            ldsm4(B, ntOff); ldsm4(B + 4, ntOff + 64);
            #pragma unroll
            for (int ks = 0; ks < 4; ++ks) {
                mma16(d0, AHI[0][ks], &B[2 * ks]);
                mma16(d1, AHI[1][ks], &B[2 * ks]);
            }
            ldsm4(B, ntOff + 128); ldsm4(B + 4, ntOff + 192);
            #pragma unroll
            for (int ks = 4; ks < 8; ++ks) {
                mma16(d0, AHI[0][ks], &B[2 * (ks - 4)]);
                mma16(d1, AHI[1][ks], &B[2 * (ks - 4)]);
            }
            const int c0 = c * NCHUNK_P + nt * 8 + 2 * qi;
            #pragma unroll
            for (int q = 0; q < 4; ++q) {
                const float da = (q < 2) ? d0[q * 2] : d1[(q - 2) * 2];
                const float db = (q < 2) ? d0[q * 2 + 1] : d1[(q - 2) * 2 + 1];
                if (da > v1a[q]) { v2a[q] = v1a[q]; v1a[q] = da; i1a[q] = c0; }
                else if (da > v2a[q]) v2a[q] = da;
                if (db > v1a[q]) { v2a[q] = v1a[q]; v1a[q] = db; i1a[q] = c0 + 1; }
                else if (db > v2a[q]) v2a[q] = db;
            }
        }
        if (c < NCHUNKS - 1) cp_wait0();
        __syncthreads();
    }

    // quad reduce top-2 (lanes of a quad hold disjoint cluster columns)
    #pragma unroll
    for (int m = 1; m <= 2; m <<= 1) {
        #pragma unroll
        for (int q = 0; q < 4; ++q) {
            float ov1 = __shfl_xor_sync(0xffffffffu, v1a[q], m);
            int   oi1 = __shfl_xor_sync(0xffffffffu, i1a[q], m);
            float ov2 = __shfl_xor_sync(0xffffffffu, v2a[q], m);
            if (ov1 > v1a[q]) {
                v2a[q] = fmaxf(v1a[q], ov2); v1a[q] = ov1; i1a[q] = oi1;
            } else if (ov1 == v1a[q]) {
                v2a[q] = v1a[q];                     // exact tie -> force flag
                i1a[q] = min(i1a[q], oi1);
            } else {
                v2a[q] = fmaxf(v2a[q], ov1);
            }
        }
    }

    if (qi == 0) {
        #pragma unroll
        for (int q = 0; q < 4; ++q) {
            const int rl = (q >> 1) * 128 + wid * 16 + (q & 1) * 8 + g;
            if (v1a[q] - v2a[q] > C2_CERT * sqrtf(nrm2[q])) {
                rowBest[rl] = i1a[q];
            } else {
                rowBest[rl] = -1;
                int pos = atomicAdd(&g_nF, 1);
                g_flag[pos] = rowBase + rl;
            }
        }
    }
    __syncthreads();

    // ---- scatter certified rows ----
    {
        int rb = rowBest[tid];
        if (rb >= 0) atomicAdd(&g_counts[rb], 1.0f);
    }
    const float4* e4 = (const float4*)ebase;
    #pragma unroll 4
    for (int it = 0; it < 32; ++it) {
        int idx = it * 256 + tid;
        int r  = idx >> 5;
        int c4 = idx & 31;
        int rb = rowBest[r];
        if (rb >= 0) red4(&g_sums[rb * DIM + c4 * 4], e4[r * 32 + c4]);
    }
}

// ---------------------------------------------------------------------------
// RefineA: hi-fp16 GEMM on gathered 128-row flagged tiles with top-4 tracking.
// Emits exact-candidate triples (listA) or full-scan rows (listB).
__global__ void __launch_bounds__(256, 2)
refineA_kernel(const float* __restrict__ emb) {
    extern __shared__ char dsm[];
    const u32 sbase = smem_u32(dsm);
    int* rowIdx = (int*)(dsm + 2 * HI_BLK);

    const int tid  = threadIdx.x;
    const int wid  = tid >> 5;
    const int lane = tid & 31;
    const int g    = lane >> 2;
    const int qi   = lane & 3;

    const int nf = *(volatile int*)&g_nF;
    const int nTiles = (nf + 127) >> 7;
    const u32 laneOff = (u32)((lane & 7) * BROW_B + (lane >> 3) * 16);

    for (int t = blockIdx.x; t < nTiles; t += gridDim.x) {
        __syncthreads();
        if (tid < 128) {
            int srci = t * 128 + tid;
            rowIdx[tid] = (srci < nf) ? g_flag[srci] : -1;
        }
        __syncthreads();

        const int r0 = rowIdx[wid * 16 + g];
        const int r1 = rowIdx[wid * 16 + g + 8];
        const float* e0 = emb + (size_t)max(r0, 0) * DIM;
        const float* e1 = emb + (size_t)max(r1, 0) * DIM;

        u32 AHI[8][4];
        float nrm2[2] = {0.f, 0.f};
        #pragma unroll
        for (int ks = 0; ks < 8; ++ks) {
            const int c0 = ks * 16 + 2 * qi;
            float2 v0 = *(const float2*)(e0 + c0);
            float2 v1 = *(const float2*)(e1 + c0);
            float2 v2 = *(const float2*)(e0 + c0 + 8);
            float2 v3 = *(const float2*)(e1 + c0 + 8);
            AHI[ks][0] = hi2(v0); AHI[ks][1] = hi2(v1);
            AHI[ks][2] = hi2(v2); AHI[ks][3] = hi2(v3);
            nrm2[0] += v0.x * v0.x + v0.y * v0.y + v2.x * v2.x + v2.y * v2.y;
            nrm2[1] += v1.x * v1.x + v1.y * v1.y + v3.x * v3.x + v3.y * v3.y;
        }
        #pragma unroll
        for (int m = 1; m <= 2; m <<= 1) {
            nrm2[0] += __shfl_xor_sync(0xffffffffu, nrm2[0], m);
            nrm2[1] += __shfl_xor_sync(0xffffffffu, nrm2[1], m);
        }

        // stage chunk 0
        #pragma unroll
        for (int j = 0; j < 9; ++j) {
            int idx = j * 256 + tid;
            if (idx < HI_CP) cp16(sbase + idx * 16, g_Bimg + idx * 16);
        }
        cp_commit(); cp_wait0();
        __syncthreads();

        float V1[2], V2[2], V3[2], V4[2];
        int   I1[2], I2[2], I3[2];
        #pragma unroll
        for (int q = 0; q < 2; ++q) {
            V1[q] = V2[q] = V3[q] = V4[q] = -3.4e38f;
            I1[q] = I2[q] = I3[q] = 0;
        }

        for (int c = 0; c < NCHUNKS; ++c) {
            const u32 bb = sbase + (u32)(c & 1) * HI_BLK;
            if (c < NCHUNKS - 1) {
                const char* src = g_Bimg + (size_t)(c + 1) * HI_BLK;
                const u32 nb = sbase + (u32)((c + 1) & 1) * HI_BLK;
                #pragma unroll
                for (int j = 0; j < 9; ++j) {
                    int idx = j * 256 + tid;
                    if (idx < HI_CP) cp16(nb + idx * 16, src + idx * 16);
                }
                cp_commit();
            }
            #pragma unroll 1
            for (int nt = 0; nt < 16; ++nt) {
                float d[4] = {0.f, 0.f, 0.f, 0.f};
                u32 B[8];
                const u32 ntOff = bb + (u32)nt * (8 * BROW_B) + laneOff;
                ldsm4(B, ntOff); ldsm4(B + 4, ntOff + 64);
                #pragma unroll
                for (int ks = 0; ks < 4; ++ks) mma16(d, AHI[ks], &B[2 * ks]);
                ldsm4(B, ntOff + 128); ldsm4(B + 4, ntOff + 192);
                #pragma unroll
                for (int ks = 4; ks < 8; ++ks) mma16(d, AHI[ks], &B[2 * (ks - 4)]);

                const int c0 = c * NCHUNK_P + nt * 8 + 2 * qi;
                fold4(d[0], c0,     V1[0], I1[0], V2[0], I2[0], V3[0], I3[0], V4[0]);
                fold4(d[1], c0 + 1, V1[0], I1[0], V2[0], I2[0], V3[0], I3[0], V4[0]);
                fold4(d[2], c0,     V1[1], I1[1], V2[1], I2[1], V3[1], I3[1], V4[1]);
                fold4(d[3], c0 + 1, V1[1], I1[1], V2[1], I2[1], V3[1], I3[1], V4[1]);
            }
            if (c < NCHUNKS - 1) cp_wait0();
            __syncthreads();
        }

        // quad merge of top-4 lists
        #pragma unroll
        for (int m = 1; m <= 2; m <<= 1) {
            #pragma unroll
            for (int q = 0; q < 2; ++q) {
                float ov1 = __shfl_xor_sync(0xffffffffu, V1[q], m);
                int   oi1 = __shfl_xor_sync(0xffffffffu, I1[q], m);
                float ov2 = __shfl_xor_sync(0xffffffffu, V2[q], m);
                int   oi2 = __shfl_xor_sync(0xffffffffu, I2[q], m);
                float ov3 = __shfl_xor_sync(0xffffffffu, V3[q], m);
                int   oi3 = __shfl_xor_sync(0xffffffffu, I3[q], m);
                float ov4 = __shfl_xor_sync(0xffffffffu, V4[q], m);
                fold4(ov1, oi1, V1[q], I1[q], V2[q], I2[q], V3[q], I3[q], V4[q]);
                fold4(ov2, oi2, V1[q], I1[q], V2[q], I2[q], V3[q], I3[q], V4[q]);
                fold4(ov3, oi3, V1[q], I1[q], V2[q], I2[q], V3[q], I3[q], V4[q]);
                V4[q] = fmaxf(V4[q], ov4);
            }
        }

        if (qi == 0) {
            #pragma unroll
            for (int q = 0; q < 2; ++q) {
                const int rl = wid * 16 + q * 8 + g;
                const int row = rowIdx[rl];
                if (row >= 0) {
                    if (V1[q] - V4[q] > C4_CERT * sqrtf(nrm2[q])) {
                        int pos = atomicAdd(&g_nA, 1);
                        g_listA[pos] = make_int4(row, I1[q], I2[q], I3[q]);
                    } else {
                        int pos = atomicAdd(&g_nB, 1);
                        g_listB[pos] = row;
                    }
                }
            }
        }
    }
}

// ---------------------------------------------------------------------------
// RefineB: warp-per-row exact fp32 resolution + scatter (R8-proven).
__global__ void __launch_bounds__(256, 2)
refineB_kernel(const float* __restrict__ emb) {
    const int w    = blockIdx.x * 8 + (threadIdx.x >> 5);
    const int lane = threadIdx.x & 31;
    const int W    = gridDim.x * 8;
    const int nA = *(volatile int*)&g_nA;
    const int nB = *(volatile int*)&g_nB;
    const float4* p4 = (const float4*)g_proto_n;

    for (int i = w; i < nA; i += W) {
        int4 ent = g_listA[i];
        const float4 ef = ((const float4*)(emb + (size_t)ent.x * DIM))[lane];
        float4 pa = p4[ent.y * 32 + lane];
        float4 pb = p4[ent.z * 32 + lane];
        float4 pc = p4[ent.w * 32 + lane];
        float d1 = fmaf(ef.x, pa.x, fmaf(ef.y, pa.y, fmaf(ef.z, pa.z, ef.w * pa.w)));
        float d2 = fmaf(ef.x, pb.x, fmaf(ef.y, pb.y, fmaf(ef.z, pb.z, ef.w * pb.w)));
        float d3 = fmaf(ef.x, pc.x, fmaf(ef.y, pc.y, fmaf(ef.z, pc.z, ef.w * pc.w)));
        #pragma unroll
        for (int m = 16; m; m >>= 1) {
            d1 += __shfl_xor_sync(0xffffffffu, d1, m);
            d2 += __shfl_xor_sync(0xffffffffu, d2, m);
            d3 += __shfl_xor_sync(0xffffffffu, d3, m);
        }
        float bv = d1; int bi = ent.y;
        if (d2 > bv || (d2 == bv && ent.z < bi)) { bv = d2; bi = ent.z; }
        if (d3 > bv || (d3 == bv && ent.w < bi)) { bv = d3; bi = ent.w; }
        if (lane == 0) atomicAdd(&g_counts[bi], 1.0f);
        red4(&g_sums[bi * DIM + lane * 4], ef);
    }

    for (int i = w; i < nB; i += W) {
        int row = g_listB[i];
        const float4 ef = ((const float4*)(emb + (size_t)row * DIM))[lane];
        float bv = -3.4e38f; int bi = 0;
        for (int k = 0; k < KCL; ++k) {
            float4 pf = p4[k * 32 + lane];
            float d = fmaf(ef.x, pf.x, fmaf(ef.y, pf.y, fmaf(ef.z, pf.z, ef.w * pf.w)));
            #pragma unroll
            for (int m = 16; m; m >>= 1) d += __shfl_xor_sync(0xffffffffu, d, m);
            if (d > bv) { bv = d; bi = k; }   // ascending k + strict > = first-max
        }
        if (lane == 0) atomicAdd(&g_counts[bi], 1.0f);
        red4(&g_sums[bi * DIM + lane * 4], ef);
    }
}

// ---------------------------------------------------------------------------
__global__ void finalize_kernel(const float* __restrict__ proto,
                                float* __restrict__ out) {
    int i = blockIdx.x * blockDim.x + threadIdx.x;
    int k = i >> 7;
    float c = g_counts[k];
    float p = proto[i];
    float m = g_sums[i] / fmaxf(c, 1.0f);
    out[i] = (c > 0.0f) ? (0.9f * p + 0.1f * m) : p;
}

// ---------------------------------------------------------------------------
extern "C" void kernel_launch(void* const* d_in, const int* in_sizes, int n_in,
                              void* d_out, int out_size) {
    const float* emb   = (const float*)d_in[0];
    const float* proto = (const float*)d_in[1];
    float* out = (float*)d_out;

    cudaFuncSetAttribute(pass1_kernel,
                         cudaFuncAttributeMaxDynamicSharedMemorySize, P1_SMEM);
    cudaFuncSetAttribute(refineA_kernel,
                         cudaFuncAttributeMaxDynamicSharedMemorySize, RA_SMEM);

    prep_kernel<<<KCL, DIM>>>(proto);
    pass1_kernel<<<BROWS / M_CTA, 256, P1_SMEM>>>(emb);
    refineA_kernel<<<148, 256, RA_SMEM>>>(emb);
    refineB_kernel<<<296, 256>>>(emb);
    finalize_kernel<<<(KCL * DIM) / 256, 256>>>(proto, out);
}

// round 10
// speedup vs baseline: 1.2527x; 1.0060x over previous
#include <cuda_runtime.h>
#include <cuda_fp16.h>
#include <cstdint>

// ---------------- problem constants ----------------
#define KCL      1024
#define DIM      128
#define BROWS    262144
#define M_CTA    512              // rows per CTA (pass 1)
#define NCHUNK_P 128              // protos per chunk
#define NCHUNKS  8                // 1024/128
#define BROW_B   272              // padded bytes per proto row -> LDSM conflict-free
#define HI_BLK   (NCHUNK_P * BROW_B)        // 34816 bytes per hi chunk
#define HI_CP    (HI_BLK / 16)              // 2176 cp.async ops per chunk
// hi-pass worst-case error: delta <= 9.9e-4*||e||; 2*delta = 1.97e-3
#define C2_CERT  2.3e-3f          // pass-1 v1-v2 certification (17% margin)
#define C4_CERT  2.3e-3f          // refineA v1-v4 top-3-candidate certification

#define P1_SMEM  (2 * HI_BLK + 2048)        // hi double buffer + rowBest[512]
#define RA_SMEM  (2 * HI_BLK + 1024)        // hi double buffer + rowIdx[128]

typedef uint32_t u32;

// ---------------- device scratch (no allocs) ----------------
__device__ __align__(16) char  g_Bimg[NCHUNKS * HI_BLK];  // hi fp16 proto image (padded)
__device__ __align__(16) float g_proto_n[KCL * DIM];      // fp32 normalized protos
__device__ __align__(16) float g_sums[KCL * DIM];
__device__ float g_counts[KCL];
__device__ int   g_flag[BROWS];    // rows uncertified by pass-1
__device__ int4  g_listA[BROWS];   // (row, i1, i2, i3) exact-candidate rows
__device__ int   g_listB[BROWS];   // rows needing full exact scan
__device__ int   g_nF, g_nA, g_nB;

// ---------------- PTX helpers (plain-sm_100-legal) ----------------
__device__ __forceinline__ u32 smem_u32(const void* p) {
    u32 a;
    asm("{ .reg .u64 t; cvta.to.shared.u64 t, %1; cvt.u32.u64 %0, t; }" : "=r"(a) : "l"(p));
    return a;
}
__device__ __forceinline__ void cp16(u32 dst, const void* src) {
    asm volatile("cp.async.cg.shared.global [%0], [%1], 16;" :: "r"(dst), "l"(src) : "memory");
}
__device__ __forceinline__ void cp_commit() { asm volatile("cp.async.commit_group;" ::: "memory"); }
__device__ __forceinline__ void cp_wait0()  { asm volatile("cp.async.wait_group 0;" ::: "memory"); }

__device__ __forceinline__ void ldsm4(u32* r, u32 addr) {
    asm volatile("ldmatrix.sync.aligned.m8n8.x4.shared.b16 {%0,%1,%2,%3}, [%4];"
                 : "=r"(r[0]), "=r"(r[1]), "=r"(r[2]), "=r"(r[3]) : "r"(addr));
}
__device__ __forceinline__ void mma16(float* d, const u32* a, const u32* b) {
    asm volatile(
        "mma.sync.aligned.m16n8k16.row.col.f32.f16.f16.f32 "
        "{%0,%1,%2,%3}, {%4,%5,%6,%7}, {%8,%9}, {%0,%1,%2,%3};"
        : "+f"(d[0]), "+f"(d[1]), "+f"(d[2]), "+f"(d[3])
        : "r"(a[0]), "r"(a[1]), "r"(a[2]), "r"(a[3]), "r"(b[0]), "r"(b[1]));
}
__device__ __forceinline__ void red4(float* gp, float4 v) {
    asm volatile("red.global.add.v4.f32 [%0], {%1,%2,%3,%4};"
                 :: "l"(gp), "f"(v.x), "f"(v.y), "f"(v.z), "f"(v.w) : "memory");
}
__device__ __forceinline__ u32 hi2(float2 v) {
    __half2 h2 = __halves2half2(__float2half_rn(v.x), __float2half_rn(v.y));
    return *(u32*)&h2;
}
// top-4 insert (values) with top-3 indices (used only in refineA, ~6% of rows)
__device__ __forceinline__ void fold4(float x, int c,
    float& v1, int& i1, float& v2, int& i2, float& v3, int& i3, float& v4) {
    if (x > v1)      { v4 = v3; v3 = v2; i3 = i2; v2 = v1; i2 = i1; v1 = x; i1 = c; }
    else if (x > v2) { v4 = v3; v3 = v2; i3 = i2; v2 = x; i2 = c; }
    else if (x > v3) { v4 = v3; v3 = x; i3 = c; }
    else if (x > v4) { v4 = x; }
}

// ---------------------------------------------------------------------------
// Prep: normalize prototypes (x / max(||x||, eps)) -> g_proto_n (fp32) and
// hi-fp16 padded image for GEMM passes. Zero sums/counts/list counters.
__global__ void prep_kernel(const float* __restrict__ proto) {
    int k = blockIdx.x, t = threadIdx.x;
    float v = proto[k * DIM + t];
    float s = v * v;
    #pragma unroll
    for (int m = 16; m; m >>= 1) s += __shfl_xor_sync(0xffffffffu, s, m);
    __shared__ float ws[4];
    if ((t & 31) == 0) ws[t >> 5] = s;
    __syncthreads();
    float pn = v * (1.0f / fmaxf(sqrtf(ws[0] + ws[1] + ws[2] + ws[3]), 1e-12f));

    g_proto_n[k * DIM + t] = pn;
    int chunk = k >> 7, n = k & 127;
    *(__half*)(g_Bimg + (size_t)chunk * HI_BLK + n * BROW_B + t * 2) = __float2half_rn(pn);

    g_sums[k * DIM + t] = 0.0f;
    if (t == 0) g_counts[k] = 0.0f;
    if (k == 0 && t == 0) { g_nF = 0; g_nA = 0; g_nB = 0; }
}

// ---------------------------------------------------------------------------
// Pass 1: hi-fp16 GEMM, M=512 per CTA (halves B staging traffic vs M=256).
// Cheap top-2 tracking; certified rows scatter; uncertified -> g_flag.
__global__ void __launch_bounds__(512, 1)
pass1_kernel(const float* __restrict__ emb) {
    extern __shared__ char dsm[];
    const u32 sbase = smem_u32(dsm);
    int* rowBest = (int*)(dsm + 2 * HI_BLK);

    const int tid  = threadIdx.x;
    const int wid  = tid >> 5;          // 0..15
    const int lane = tid & 31;
    const int g    = lane >> 2;
    const int qi   = lane & 3;
    const int rowBase = blockIdx.x * M_CTA;
    const float* ebase = emb + (size_t)rowBase * DIM;

    // ---- A hi fragments + row norms (2 m16 tiles per warp: +0, +256) ----
    u32 AHI[2][8][4];
    float nrm2[4] = {0.f, 0.f, 0.f, 0.f};
    #pragma unroll
    for (int t2 = 0; t2 < 2; ++t2) {
        const int rA = t2 * 256 + wid * 16 + g;
        #pragma unroll
        for (int ks = 0; ks < 8; ++ks) {
            const int c0 = ks * 16 + 2 * qi;
            float2 v0 = *(const float2*)(ebase + (size_t)rA * DIM + c0);
            float2 v1 = *(const float2*)(ebase + (size_t)(rA + 8) * DIM + c0);
            float2 v2 = *(const float2*)(ebase + (size_t)rA * DIM + c0 + 8);
            float2 v3 = *(const float2*)(ebase + (size_t)(rA + 8) * DIM + c0 + 8);
            AHI[t2][ks][0] = hi2(v0); AHI[t2][ks][1] = hi2(v1);
            AHI[t2][ks][2] = hi2(v2); AHI[t2][ks][3] = hi2(v3);
            nrm2[t2 * 2]     += v0.x * v0.x + v0.y * v0.y + v2.x * v2.x + v2.y * v2.y;
            nrm2[t2 * 2 + 1] += v1.x * v1.x + v1.y * v1.y + v3.x * v3.x + v3.y * v3.y;
        }
    }
    #pragma unroll
    for (int m = 1; m <= 2; m <<= 1)
        #pragma unroll
        for (int q = 0; q < 4; ++q)
            nrm2[q] += __shfl_xor_sync(0xffffffffu, nrm2[q], m);

    const u32 laneOff = (u32)((lane & 7) * BROW_B + (lane >> 3) * 16);

    // stage chunk 0
    #pragma unroll
    for (int j = 0; j < 5; ++j) {
        int idx = j * 512 + tid;
        if (idx < HI_CP) cp16(sbase + idx * 16, g_Bimg + idx * 16);
    }
    cp_commit(); cp_wait0();
    __syncthreads();

    float v1a[4], v2a[4]; int i1a[4];
    #pragma unroll
    for (int q = 0; q < 4; ++q) { v1a[q] = -3.4e38f; v2a[q] = -3.4e38f; i1a[q] = 0; }

    for (int c = 0; c < NCHUNKS; ++c) {
        const u32 bb = sbase + (u32)(c & 1) * HI_BLK;
        if (c < NCHUNKS - 1) {
            const char* src = g_Bimg + (size_t)(c + 1) * HI_BLK;
            const u32 nb = sbase + (u32)((c + 1) & 1) * HI_BLK;
            #pragma unroll
            for (int j = 0; j < 5; ++j) {
                int idx = j * 512 + tid;
                if (idx < HI_CP) cp16(nb + idx * 16, src + idx * 16);
            }
            cp_commit();
        }

        #pragma unroll 1
        for (int nt = 0; nt < 16; ++nt) {
            float d0[4] = {0.f, 0.f, 0.f, 0.f};
            float d1[4] = {0.f, 0.f, 0.f, 0.f};
            u32 B[8];
            const u32 ntOff = bb + (u32)nt * (8 * BROW_B) + laneOff;
            ldsm4(B, ntOff); ldsm4(B + 4, ntOff + 64);
            #pragma unroll
            for (int ks = 0; ks < 4; ++ks) {
                mma16(d0, AHI[0][ks], &B[2 * ks]);
                mma16(d1, AHI[1][ks], &B[2 * ks]);
            }
            ldsm4(B, ntOff + 128); ldsm4(B + 4, ntOff + 192);
            #pragma unroll
            for (int ks = 4; ks < 8; ++ks) {
                mma16(d0, AHI[0][ks], &B[2 * (ks - 4)]);
                mma16(d1, AHI[1][ks], &B[2 * (ks - 4)]);
            }
            const int c0 = c * NCHUNK_P + nt * 8 + 2 * qi;
            #pragma unroll
            for (int q = 0; q < 4; ++q) {
                const float da = (q < 2) ? d0[q * 2] : d1[(q - 2) * 2];
                const float db = (q < 2) ? d0[q * 2 + 1] : d1[(q - 2) * 2 + 1];
                if (da > v1a[q]) { v2a[q] = v1a[q]; v1a[q] = da; i1a[q] = c0; }
                else if (da > v2a[q]) v2a[q] = da;
                if (db > v1a[q]) { v2a[q] = v1a[q]; v1a[q] = db; i1a[q] = c0 + 1; }
                else if (db > v2a[q]) v2a[q] = db;
            }
        }
        if (c < NCHUNKS - 1) cp_wait0();
        __syncthreads();
    }

    // quad reduce top-2 (lanes of a quad hold disjoint cluster columns)
    #pragma unroll
    for (int m = 1; m <= 2; m <<= 1) {
        #pragma unroll
        for (int q = 0; q < 4; ++q) {
            float ov1 = __shfl_xor_sync(0xffffffffu, v1a[q], m);
            int   oi1 = __shfl_xor_sync(0xffffffffu, i1a[q], m);
            float ov2 = __shfl_xor_sync(0xffffffffu, v2a[q], m);
            if (ov1 > v1a[q]) {
                v2a[q] = fmaxf(v1a[q], ov2); v1a[q] = ov1; i1a[q] = oi1;
            } else if (ov1 == v1a[q]) {
                v2a[q] = v1a[q];                     // exact tie -> force flag
                i1a[q] = min(i1a[q], oi1);
            } else {
                v2a[q] = fmaxf(v2a[q], ov1);
            }
        }
    }

    if (qi == 0) {
        #pragma unroll
        for (int q = 0; q < 4; ++q) {
            const int rl = (q >> 1) * 256 + wid * 16 + (q & 1) * 8 + g;
            if (v1a[q] - v2a[q] > C2_CERT * sqrtf(nrm2[q])) {
                rowBest[rl] = i1a[q];
            } else {
                rowBest[rl] = -1;
                int pos = atomicAdd(&g_nF, 1);
                g_flag[pos] = rowBase + rl;
            }
        }
    }
    __syncthreads();

    // ---- scatter certified rows ----
    {
        int rb = rowBest[tid];
        if (rb >= 0) atomicAdd(&g_counts[rb], 1.0f);
    }
    const float4* e4 = (const float4*)ebase;
    #pragma unroll 4
    for (int it = 0; it < 32; ++it) {
        int idx = it * 512 + tid;
        int r  = idx >> 5;
        int c4 = idx & 31;
        int rb = rowBest[r];
        if (rb >= 0) red4(&g_sums[rb * DIM + c4 * 4], e4[r * 32 + c4]);
    }
}

// ---------------------------------------------------------------------------
// RefineA: hi-fp16 GEMM on gathered 128-row flagged tiles with top-4 tracking.
// Emits exact-candidate triples (listA) or full-scan rows (listB).
__global__ void __launch_bounds__(256, 2)
refineA_kernel(const float* __restrict__ emb) {
    extern __shared__ char dsm[];
    const u32 sbase = smem_u32(dsm);
    int* rowIdx = (int*)(dsm + 2 * HI_BLK);

    const int tid  = threadIdx.x;
    const int wid  = tid >> 5;
    const int lane = tid & 31;
    const int g    = lane >> 2;
    const int qi   = lane & 3;

    const int nf = *(volatile int*)&g_nF;
    const int nTiles = (nf + 127) >> 7;
    const u32 laneOff = (u32)((lane & 7) * BROW_B + (lane >> 3) * 16);

    for (int t = blockIdx.x; t < nTiles; t += gridDim.x) {
        __syncthreads();
        if (tid < 128) {
            int srci = t * 128 + tid;
            rowIdx[tid] = (srci < nf) ? g_flag[srci] : -1;
        }
        __syncthreads();

        const int r0 = rowIdx[wid * 16 + g];
        const int r1 = rowIdx[wid * 16 + g + 8];
        const float* e0 = emb + (size_t)max(r0, 0) * DIM;
        const float* e1 = emb + (size_t)max(r1, 0) * DIM;

        u32 AHI[8][4];
        float nrm2[2] = {0.f, 0.f};
        #pragma unroll
        for (int ks = 0; ks < 8; ++ks) {
            const int c0 = ks * 16 + 2 * qi;
            float2 v0 = *(const float2*)(e0 + c0);
            float2 v1 = *(const float2*)(e1 + c0);
            float2 v2 = *(const float2*)(e0 + c0 + 8);
            float2 v3 = *(const float2*)(e1 + c0 + 8);
            AHI[ks][0] = hi2(v0); AHI[ks][1] = hi2(v1);
            AHI[ks][2] = hi2(v2); AHI[ks][3] = hi2(v3);
            nrm2[0] += v0.x * v0.x + v0.y * v0.y + v2.x * v2.x + v2.y * v2.y;
            nrm2[1] += v1.x * v1.x + v1.y * v1.y + v3.x * v3.x + v3.y * v3.y;
        }
        #pragma unroll
        for (int m = 1; m <= 2; m <<= 1) {
            nrm2[0] += __shfl_xor_sync(0xffffffffu, nrm2[0], m);
            nrm2[1] += __shfl_xor_sync(0xffffffffu, nrm2[1], m);
        }

        // stage chunk 0
        #pragma unroll
        for (int j = 0; j < 9; ++j) {
            int idx = j * 256 + tid;
            if (idx < HI_CP) cp16(sbase + idx * 16, g_Bimg + idx * 16);
        }
        cp_commit(); cp_wait0();
        __syncthreads();

        float V1[2], V2[2], V3[2], V4[2];
        int   I1[2], I2[2], I3[2];
        #pragma unroll
        for (int q = 0; q < 2; ++q) {
            V1[q] = V2[q] = V3[q] = V4[q] = -3.4e38f;
            I1[q] = I2[q] = I3[q] = 0;
        }

        for (int c = 0; c < NCHUNKS; ++c) {
            const u32 bb = sbase + (u32)(c & 1) * HI_BLK;
            if (c < NCHUNKS - 1) {
                const char* src = g_Bimg + (size_t)(c + 1) * HI_BLK;
                const u32 nb = sbase + (u32)((c + 1) & 1) * HI_BLK;
                #pragma unroll
                for (int j = 0; j < 9; ++j) {
                    int idx = j * 256 + tid;
                    if (idx < HI_CP) cp16(nb + idx * 16, src + idx * 16);
                }
                cp_commit();
            }
            #pragma unroll 1
            for (int nt = 0; nt < 16; ++nt) {
                float d[4] = {0.f, 0.f, 0.f, 0.f};
                u32 B[8];
                const u32 ntOff = bb + (u32)nt * (8 * BROW_B) + laneOff;
                ldsm4(B, ntOff); ldsm4(B + 4, ntOff + 64);
                #pragma unroll
                for (int ks = 0; ks < 4; ++ks) mma16(d, AHI[ks], &B[2 * ks]);
                ldsm4(B, ntOff + 128); ldsm4(B + 4, ntOff + 192);
                #pragma unroll
                for (int ks = 4; ks < 8; ++ks) mma16(d, AHI[ks], &B[2 * (ks - 4)]);

                const int c0 = c * NCHUNK_P + nt * 8 + 2 * qi;
                fold4(d[0], c0,     V1[0], I1[0], V2[0], I2[0], V3[0], I3[0], V4[0]);
                fold4(d[1], c0 + 1, V1[0], I1[0], V2[0], I2[0], V3[0], I3[0], V4[0]);
                fold4(d[2], c0,     V1[1], I1[1], V2[1], I2[1], V3[1], I3[1], V4[1]);
                fold4(d[3], c0 + 1, V1[1], I1[1], V2[1], I2[1], V3[1], I3[1], V4[1]);
            }
            if (c < NCHUNKS - 1) cp_wait0();
            __syncthreads();
        }

        // quad merge of top-4 lists
        #pragma unroll
        for (int m = 1; m <= 2; m <<= 1) {
            #pragma unroll
            for (int q = 0; q < 2; ++q) {
                float ov1 = __shfl_xor_sync(0xffffffffu, V1[q], m);
                int   oi1 = __shfl_xor_sync(0xffffffffu, I1[q], m);
                float ov2 = __shfl_xor_sync(0xffffffffu, V2[q], m);
                int   oi2 = __shfl_xor_sync(0xffffffffu, I2[q], m);
                float ov3 = __shfl_xor_sync(0xffffffffu, V3[q], m);
                int   oi3 = __shfl_xor_sync(0xffffffffu, I3[q], m);
                float ov4 = __shfl_xor_sync(0xffffffffu, V4[q], m);
                fold4(ov1, oi1, V1[q], I1[q], V2[q], I2[q], V3[q], I3[q], V4[q]);
                fold4(ov2, oi2, V1[q], I1[q], V2[q], I2[q], V3[q], I3[q], V4[q]);
                fold4(ov3, oi3, V1[q], I1[q], V2[q], I2[q], V3[q], I3[q], V4[q]);
                V4[q] = fmaxf(V4[q], ov4);
            }
        }

        if (qi == 0) {
            #pragma unroll
            for (int q = 0; q < 2; ++q) {
                const int rl = wid * 16 + q * 8 + g;
                const int row = rowIdx[rl];
                if (row >= 0) {
                    if (V1[q] - V4[q] > C4_CERT * sqrtf(nrm2[q])) {
                        int pos = atomicAdd(&g_nA, 1);
                        g_listA[pos] = make_int4(row, I1[q], I2[q], I3[q]);
                    } else {
                        int pos = atomicAdd(&g_nB, 1);
                        g_listB[pos] = row;
                    }
                }
            }
        }
    }
}

// ---------------------------------------------------------------------------
// RefineB: warp-per-row exact fp32 resolution + scatter.
// listB full scan uses a 4-way interleaved k-loop (pipelined shuffle chains).
__global__ void __launch_bounds__(256, 2)
refineB_kernel(const float* __restrict__ emb) {
    const int w    = blockIdx.x * 8 + (threadIdx.x >> 5);
    const int lane = threadIdx.x & 31;
    const int W    = gridDim.x * 8;
    const int nA = *(volatile int*)&g_nA;
    const int nB = *(volatile int*)&g_nB;
    const float4* p4 = (const float4*)g_proto_n;

    for (int i = w; i < nA; i += W) {
        int4 ent = g_listA[i];
        const float4 ef = ((const float4*)(emb + (size_t)ent.x * DIM))[lane];
        float4 pa = p4[ent.y * 32 + lane];
        float4 pb = p4[ent.z * 32 + lane];
        float4 pc = p4[ent.w * 32 + lane];
        float d1 = fmaf(ef.x, pa.x, fmaf(ef.y, pa.y, fmaf(ef.z, pa.z, ef.w * pa.w)));
        float d2 = fmaf(ef.x, pb.x, fmaf(ef.y, pb.y, fmaf(ef.z, pb.z, ef.w * pb.w)));
        float d3 = fmaf(ef.x, pc.x, fmaf(ef.y, pc.y, fmaf(ef.z, pc.z, ef.w * pc.w)));
        #pragma unroll
        for (int m = 16; m; m >>= 1) {
            d1 += __shfl_xor_sync(0xffffffffu, d1, m);
            d2 += __shfl_xor_sync(0xffffffffu, d2, m);
            d3 += __shfl_xor_sync(0xffffffffu, d3, m);
        }
        float bv = d1; int bi = ent.y;
        if (d2 > bv || (d2 == bv && ent.z < bi)) { bv = d2; bi = ent.z; }
        if (d3 > bv || (d3 == bv && ent.w < bi)) { bv = d3; bi = ent.w; }
        if (lane == 0) atomicAdd(&g_counts[bi], 1.0f);
        red4(&g_sums[bi * DIM + lane * 4], ef);
    }

    for (int i = w; i < nB; i += W) {
        int row = g_listB[i];
        const float4 ef = ((const float4*)(emb + (size_t)row * DIM))[lane];
        float bv = -3.4e38f; int bi = 0;
        for (int k = 0; k < KCL; k += 4) {
            float d[4];
            #pragma unroll
            for (int u = 0; u < 4; ++u) {
                float4 pf = p4[(k + u) * 32 + lane];
                d[u] = fmaf(ef.x, pf.x, fmaf(ef.y, pf.y, fmaf(ef.z, pf.z, ef.w * pf.w)));
            }
            #pragma unroll
            for (int m = 16; m; m >>= 1) {
                #pragma unroll
                for (int u = 0; u < 4; ++u)
                    d[u] += __shfl_xor_sync(0xffffffffu, d[u], m);
            }
            #pragma unroll
            for (int u = 0; u < 4; ++u)
                if (d[u] > bv) { bv = d[u]; bi = k + u; }   // ascending k = first-max
        }
        if (lane == 0) atomicAdd(&g_counts[bi], 1.0f);
        red4(&g_sums[bi * DIM + lane * 4], ef);
    }
}

// ---------------------------------------------------------------------------
__global__ void finalize_kernel(const float* __restrict__ proto,
                                float* __restrict__ out) {
    int i = blockIdx.x * blockDim.x + threadIdx.x;
    int k = i >> 7;
    float c = g_counts[k];
    float p = proto[i];
    float m = g_sums[i] / fmaxf(c, 1.0f);
    out[i] = (c > 0.0f) ? (0.9f * p + 0.1f * m) : p;
}

// ---------------------------------------------------------------------------
extern "C" void kernel_launch(void* const* d_in, const int* in_sizes, int n_in,
                              void* d_out, int out_size) {
    const float* emb   = (const float*)d_in[0];
    const float* proto = (const float*)d_in[1];
    float* out = (float*)d_out;

    cudaFuncSetAttribute(pass1_kernel,
                         cudaFuncAttributeMaxDynamicSharedMemorySize, P1_SMEM);
    cudaFuncSetAttribute(refineA_kernel,
                         cudaFuncAttributeMaxDynamicSharedMemorySize, RA_SMEM);

    prep_kernel<<<KCL, DIM>>>(proto);
    pass1_kernel<<<BROWS / M_CTA, 512, P1_SMEM>>>(emb);
    refineA_kernel<<<148, 256, RA_SMEM>>>(emb);
    refineB_kernel<<<1184, 256>>>(emb);
    finalize_kernel<<<(KCL * DIM) / 256, 256>>>(proto, out);
}

// round 12
// speedup vs baseline: 1.3309x; 1.0624x over previous
#include <cuda_runtime.h>
#include <cuda_fp16.h>
#include <cstdint>

// ---------------- problem constants ----------------
#define KCL      1024
#define DIM      128
#define BROWS    262144
#define M_CTA    256              // rows per CTA (pass 1)
#define NCHUNK_P 128              // protos per chunk
#define NCHUNKS  8                // 1024/128
#define BROW_B   272              // padded bytes per proto row -> LDSM conflict-free
#define HI_BLK   (NCHUNK_P * BROW_B)        // 34816 bytes per hi chunk
// hi-pass worst-case error: delta <= 9.9e-4*||e||; 2*delta = 1.97e-3
#define C2_CERT  2.3e-3f          // pass-1 v1-v2 certification
#define C4_CERT  2.3e-3f          // refineA v1-v4 top-3-candidate certification

// pass1 smem: buf[2] + rowBest[256] + mbar[2]
#define P1_MB    (2 * HI_BLK + 1024)
#define P1_SMEM  (P1_MB + 32)
// refineA smem: buf[2] + rowIdx[128] + cCand[128] + mbar[2]
#define RA_RI    (2 * HI_BLK)
#define RA_CC    (RA_RI + 512)
#define RA_MB    (RA_CC + 2048)
#define RA_SMEM  (RA_MB + 32)

typedef uint32_t u32;

// ---------------- device scratch (no allocs) ----------------
__device__ __align__(16) char  g_Bimg[NCHUNKS * HI_BLK];  // hi fp16 proto image (padded)
__device__ __align__(16) float g_proto_n[KCL * DIM];      // fp32 normalized protos
__device__ __align__(16) float g_sums[KCL * DIM];
__device__ float g_counts[KCL];
__device__ int   g_flag[BROWS];    // rows uncertified by pass-1
__device__ int   g_listB[BROWS];   // rows needing full exact scan
__device__ int   g_nF, g_nB;

// ---------------- PTX helpers (plain-sm_100-legal: sm_80/sm_90 ops) ----------
__device__ __forceinline__ u32 smem_u32(const void* p) {
    u32 a;
    asm("{ .reg .u64 t; cvta.to.shared.u64 t, %1; cvt.u32.u64 %0, t; }" : "=r"(a) : "l"(p));
    return a;
}
__device__ __forceinline__ void mbar_init(u32 a, u32 cnt) {
    asm volatile("mbarrier.init.shared.b64 [%0], %1;" :: "r"(a), "r"(cnt) : "memory");
}
__device__ __forceinline__ void mbar_expect_tx(u32 a, u32 bytes) {
    asm volatile("mbarrier.arrive.expect_tx.shared.b64 _, [%0], %1;"
                 :: "r"(a), "r"(bytes) : "memory");
}
__device__ __forceinline__ void mbar_wait(u32 a, u32 parity) {
    asm volatile(
        "{\n\t.reg .pred P;\n"
        "WL_%=:\n\t"
        "mbarrier.try_wait.parity.acquire.cta.shared::cta.b64 P, [%0], %1, 0x989680;\n\t"
        "@P bra WD_%=;\n\t"
        "bra WL_%=;\n"
        "WD_%=:\n\t}"
        :: "r"(a), "r"(parity) : "memory");
}
// bulk copy global -> shared, completion via mbarrier (SASS: UBLKCP.S.G)
__device__ __forceinline__ void bulk_g2s(u32 dst, const void* src, u32 bytes, u32 mbar) {
    asm volatile(
        "cp.async.bulk.shared::cluster.global.mbarrier::complete_tx::bytes "
        "[%0], [%1], %2, [%3];"
        :: "r"(dst), "l"(src), "r"(bytes), "r"(mbar) : "memory");
}
__device__ __forceinline__ void ldsm4(u32* r, u32 addr) {
    asm volatile("ldmatrix.sync.aligned.m8n8.x4.shared.b16 {%0,%1,%2,%3}, [%4];"
                 : "=r"(r[0]), "=r"(r[1]), "=r"(r[2]), "=r"(r[3]) : "r"(addr));
}
__device__ __forceinline__ void mma16(float* d, const u32* a, const u32* b) {
    asm volatile(
        "mma.sync.aligned.m16n8k16.row.col.f32.f16.f16.f32 "
        "{%0,%1,%2,%3}, {%4,%5,%6,%7}, {%8,%9}, {%0,%1,%2,%3};"
        : "+f"(d[0]), "+f"(d[1]), "+f"(d[2]), "+f"(d[3])
        : "r"(a[0]), "r"(a[1]), "r"(a[2]), "r"(a[3]), "r"(b[0]), "r"(b[1]));
}
__device__ __forceinline__ void red4(float* gp, float4 v) {
    asm volatile("red.global.add.v4.f32 [%0], {%1,%2,%3,%4};"
                 :: "l"(gp), "f"(v.x), "f"(v.y), "f"(v.z), "f"(v.w) : "memory");
}
__device__ __forceinline__ u32 hi2(float2 v) {
    __half2 h2 = __halves2half2(__float2half_rn(v.x), __float2half_rn(v.y));
    return *(u32*)&h2;
}
// top-4 insert (values) with top-3 indices (refineA only)
__device__ __forceinline__ void fold4(float x, int c,
    float& v1, int& i1, float& v2, int& i2, float& v3, int& i3, float& v4) {
    if (x > v1)      { v4 = v3; v3 = v2; i3 = i2; v2 = v1; i2 = i1; v1 = x; i1 = c; }
    else if (x > v2) { v4 = v3; v3 = v2; i3 = i2; v2 = x; i2 = c; }
    else if (x > v3) { v4 = v3; v3 = x; i3 = c; }
    else if (x > v4) { v4 = x; }
}

// ---------------------------------------------------------------------------
// Prep: normalize prototypes (x / max(||x||, eps)) -> g_proto_n (fp32) and
// hi-fp16 padded image. Zero sums/counts/list counters.
__global__ void prep_kernel(const float* __restrict__ proto) {
    int k = blockIdx.x, t = threadIdx.x;
    float v = proto[k * DIM + t];
    float s = v * v;
    #pragma unroll
    for (int m = 16; m; m >>= 1) s += __shfl_xor_sync(0xffffffffu, s, m);
    __shared__ float ws[4];
    if ((t & 31) == 0) ws[t >> 5] = s;
    __syncthreads();
    float pn = v * (1.0f / fmaxf(sqrtf(ws[0] + ws[1] + ws[2] + ws[3]), 1e-12f));

    g_proto_n[k * DIM + t] = pn;
    int chunk = k >> 7, n = k & 127;
    *(__half*)(g_Bimg + (size_t)chunk * HI_BLK + n * BROW_B + t * 2) = __float2half_rn(pn);

    g_sums[k * DIM + t] = 0.0f;
    if (t == 0) g_counts[k] = 0.0f;
    if (k == 0 && t == 0) { g_nF = 0; g_nB = 0; }
}

// ---------------------------------------------------------------------------
// Pass 1: hi-fp16 GEMM, bulk-copy staging, cheap top-2 tracking.
// Certified rows scatter; uncertified -> g_flag.
__global__ void __launch_bounds__(256, 2)
pass1_kernel(const float* __restrict__ emb) {
    extern __shared__ char dsm[];
    const u32 sbase = smem_u32(dsm);
    int* rowBest = (int*)(dsm + 2 * HI_BLK);
    const u32 mb0 = sbase + P1_MB, mb1 = mb0 + 8;

    const int tid  = threadIdx.x;
    const int wid  = tid >> 5;
    const int lane = tid & 31;
    const int g    = lane >> 2;
    const int qi   = lane & 3;
    const int rowBase = blockIdx.x * M_CTA;
    const float* ebase = emb + (size_t)rowBase * DIM;

    if (tid == 0) { mbar_init(mb0, 1); mbar_init(mb1, 1); }
    __syncthreads();
    if (tid == 0) {
        mbar_expect_tx(mb0, HI_BLK); bulk_g2s(sbase, g_Bimg, HI_BLK, mb0);
        mbar_expect_tx(mb1, HI_BLK); bulk_g2s(sbase + HI_BLK, g_Bimg + HI_BLK, HI_BLK, mb1);
    }

    // ---- A hi fragments + row norms (overlaps with bulk latency) ----
    u32 AHI[2][8][4];
    float nrm2[4] = {0.f, 0.f, 0.f, 0.f};
    #pragma unroll
    for (int t2 = 0; t2 < 2; ++t2) {
        const int rA = t2 * 128 + wid * 16 + g;
        #pragma unroll
        for (int ks = 0; ks < 8; ++ks) {
            const int c0 = ks * 16 + 2 * qi;
            float2 v0 = *(const float2*)(ebase + (size_t)rA * DIM + c0);
            float2 v1 = *(const float2*)(ebase + (size_t)(rA + 8) * DIM + c0);
            float2 v2 = *(const float2*)(ebase + (size_t)rA * DIM + c0 + 8);
            float2 v3 = *(const float2*)(ebase + (size_t)(rA + 8) * DIM + c0 + 8);
            AHI[t2][ks][0] = hi2(v0); AHI[t2][ks][1] = hi2(v1);
            AHI[t2][ks][2] = hi2(v2); AHI[t2][ks][3] = hi2(v3);
            nrm2[t2 * 2]     += v0.x * v0.x + v0.y * v0.y + v2.x * v2.x + v2.y * v2.y;
            nrm2[t2 * 2 + 1] += v1.x * v1.x + v1.y * v1.y + v3.x * v3.x + v3.y * v3.y;
        }
    }
    #pragma unroll
    for (int m = 1; m <= 2; m <<= 1)
        #pragma unroll
        for (int q = 0; q < 4; ++q)
            nrm2[q] += __shfl_xor_sync(0xffffffffu, nrm2[q], m);

    const u32 laneOff = (u32)((lane & 7) * BROW_B + (lane >> 3) * 16);

    float v1a[4], v2a[4]; int i1a[4];
    #pragma unroll
    for (int q = 0; q < 4; ++q) { v1a[q] = -3.4e38f; v2a[q] = -3.4e38f; i1a[q] = 0; }

    for (int c = 0; c < NCHUNKS; ++c) {
        const int s = c & 1;
        mbar_wait(s ? mb1 : mb0, (u32)((c >> 1) & 1));
        const u32 bb = sbase + (u32)s * HI_BLK;

        #pragma unroll 1
        for (int nt = 0; nt < 16; ++nt) {
            float d0[4] = {0.f, 0.f, 0.f, 0.f};
            float d1[4] = {0.f, 0.f, 0.f, 0.f};
            u32 B[8];
            const u32 ntOff = bb + (u32)nt * (8 * BROW_B) + laneOff;
            ldsm4(B, ntOff); ldsm4(B + 4, ntOff + 64);
            #pragma unroll
            for (int ks = 0; ks < 4; ++ks) {
                mma16(d0, AHI[0][ks], &B[2 * ks]);
                mma16(d1, AHI[1][ks], &B[2 * ks]);
            }
            ldsm4(B, ntOff + 128); ldsm4(B + 4, ntOff + 192);
            #pragma unroll
            for (int ks = 4; ks < 8; ++ks) {
                mma16(d0, AHI[0][ks], &B[2 * (ks - 4)]);
                mma16(d1, AHI[1][ks], &B[2 * (ks - 4)]);
            }
            const int c0 = c * NCHUNK_P + nt * 8 + 2 * qi;
            #pragma unroll
            for (int q = 0; q < 4; ++q) {
                const float da = (q < 2) ? d0[q * 2] : d1[(q - 2) * 2];
                const float db = (q < 2) ? d0[q * 2 + 1] : d1[(q - 2) * 2 + 1];
                if (da > v1a[q]) { v2a[q] = v1a[q]; v1a[q] = da; i1a[q] = c0; }
                else if (da > v2a[q]) v2a[q] = da;
                if (db > v1a[q]) { v2a[q] = v1a[q]; v1a[q] = db; i1a[q] = c0 + 1; }
                else if (db > v2a[q]) v2a[q] = db;
            }
        }
        __syncthreads();
        if (c + 2 < NCHUNKS && tid == 0) {
            const u32 mb = s ? mb1 : mb0;
            mbar_expect_tx(mb, HI_BLK);
            bulk_g2s(sbase + (u32)s * HI_BLK, g_Bimg + (size_t)(c + 2) * HI_BLK, HI_BLK, mb);
        }
    }

    // quad reduce top-2 (lanes of a quad hold disjoint cluster columns)
    #pragma unroll
    for (int m = 1; m <= 2; m <<= 1) {
        #pragma unroll
        for (int q = 0; q < 4; ++q) {
            float ov1 = __shfl_xor_sync(0xffffffffu, v1a[q], m);
            int   oi1 = __shfl_xor_sync(0xffffffffu, i1a[q], m);
            float ov2 = __shfl_xor_sync(0xffffffffu, v2a[q], m);
            if (ov1 > v1a[q]) {
                v2a[q] = fmaxf(v1a[q], ov2); v1a[q] = ov1; i1a[q] = oi1;
            } else if (ov1 == v1a[q]) {
                v2a[q] = v1a[q];                     // exact tie -> force flag
                i1a[q] = min(i1a[q], oi1);
            } else {
                v2a[q] = fmaxf(v2a[q], ov1);
            }
        }
    }

    if (qi == 0) {
        #pragma unroll
        for (int q = 0; q < 4; ++q) {
            const int rl = (q >> 1) * 128 + wid * 16 + (q & 1) * 8 + g;
            if (v1a[q] - v2a[q] > C2_CERT * sqrtf(nrm2[q])) {
                rowBest[rl] = i1a[q];
            } else {
                rowBest[rl] = -1;
                int pos = atomicAdd(&g_nF, 1);
                g_flag[pos] = rowBase + rl;
            }
        }
    }
    __syncthreads();

    // ---- scatter certified rows ----
    {
        int rb = rowBest[tid];
        if (rb >= 0) atomicAdd(&g_counts[rb], 1.0f);
    }
    const float4* e4 = (const float4*)ebase;
    #pragma unroll 4
    for (int it = 0; it < 32; ++it) {
        int idx = it * 256 + tid;
        int r  = idx >> 5;
        int c4 = idx & 31;
        int rb = rowBest[r];
        if (rb >= 0) red4(&g_sums[rb * DIM + c4 * 4], e4[r * 32 + c4]);
    }
}

// ---------------------------------------------------------------------------
// RefineA: hi-fp16 GEMM on gathered 128-row flagged tiles (bulk staging) with
// top-4 tracking, then INLINE exact fp32 resolution of the top-3 candidates
// + scatter. Rows failing the top-3 cert go to g_listB.
__global__ void __launch_bounds__(256, 2)
refineA_kernel(const float* __restrict__ emb) {
    extern __shared__ char dsm[];
    const u32 sbase = smem_u32(dsm);
    int*  rowIdx = (int*)(dsm + RA_RI);
    int4* cCand  = (int4*)(dsm + RA_CC);
    const u32 mb0 = sbase + RA_MB, mb1 = mb0 + 8;

    const int tid  = threadIdx.x;
    const int wid  = tid >> 5;
    const int lane = tid & 31;
    const int g    = lane >> 2;
    const int qi   = lane & 3;

    const int nf = *(volatile int*)&g_nF;
    const int nTiles = (nf + 127) >> 7;
    const u32 laneOff = (u32)((lane & 7) * BROW_B + (lane >> 3) * 16);
    const float4* p4 = (const float4*)g_proto_n;

    if (tid == 0) { mbar_init(mb0, 1); mbar_init(mb1, 1); }
    __syncthreads();

    int pc0 = 0, pc1 = 0;   // per-stage completed-phase counters (cross-tile)

    for (int t = blockIdx.x; t < nTiles; t += gridDim.x) {
        if (tid < 128) {
            int srci = t * 128 + tid;
            rowIdx[tid] = (srci < nf) ? g_flag[srci] : -1;
        }
        __syncthreads();
        if (tid == 0) {
            mbar_expect_tx(mb0, HI_BLK); bulk_g2s(sbase, g_Bimg, HI_BLK, mb0);
            mbar_expect_tx(mb1, HI_BLK); bulk_g2s(sbase + HI_BLK, g_Bimg + HI_BLK, HI_BLK, mb1);
        }

        const int r0 = rowIdx[wid * 16 + g];
        const int r1 = rowIdx[wid * 16 + g + 8];
        const float* e0 = emb + (size_t)max(r0, 0) * DIM;
        const float* e1 = emb + (size_t)max(r1, 0) * DIM;

        u32 AHI[8][4];
        float nrm2[2] = {0.f, 0.f};
        #pragma unroll
        for (int ks = 0; ks < 8; ++ks) {
            const int c0 = ks * 16 + 2 * qi;
            float2 v0 = *(const float2*)(e0 + c0);
            float2 v1 = *(const float2*)(e1 + c0);
            float2 v2 = *(const float2*)(e0 + c0 + 8);
            float2 v3 = *(const float2*)(e1 + c0 + 8);
            AHI[ks][0] = hi2(v0); AHI[ks][1] = hi2(v1);
            AHI[ks][2] = hi2(v2); AHI[ks][3] = hi2(v3);
            nrm2[0] += v0.x * v0.x + v0.y * v0.y + v2.x * v2.x + v2.y * v2.y;
            nrm2[1] += v1.x * v1.x + v1.y * v1.y + v3.x * v3.x + v3.y * v3.y;
        }
        #pragma unroll
        for (int m = 1; m <= 2; m <<= 1) {
            nrm2[0] += __shfl_xor_sync(0xffffffffu, nrm2[0], m);
            nrm2[1] += __shfl_xor_sync(0xffffffffu, nrm2[1], m);
        }

        float V1[2], V2[2], V3[2], V4[2];
        int   I1[2], I2[2], I3[2];
        #pragma unroll
        for (int q = 0; q < 2; ++q) {
            V1[q] = V2[q] = V3[q] = V4[q] = -3.4e38f;
            I1[q] = I2[q] = I3[q] = 0;
        }

        for (int c = 0; c < NCHUNKS; ++c) {
            const int s = c & 1;
            mbar_wait(s ? mb1 : mb0, (u32)((s ? pc1 : pc0) & 1));
            const u32 bb = sbase + (u32)s * HI_BLK;

            #pragma unroll 1
            for (int nt = 0; nt < 16; ++nt) {
                float d[4] = {0.f, 0.f, 0.f, 0.f};
                u32 B[8];
                const u32 ntOff = bb + (u32)nt * (8 * BROW_B) + laneOff;
                ldsm4(B, ntOff); ldsm4(B + 4, ntOff + 64);
                #pragma unroll
                for (int ks = 0; ks < 4; ++ks) mma16(d, AHI[ks], &B[2 * ks]);
                ldsm4(B, ntOff + 128); ldsm4(B + 4, ntOff + 192);
                #pragma unroll
                for (int ks = 4; ks < 8; ++ks) mma16(d, AHI[ks], &B[2 * (ks - 4)]);

                const int c0 = c * NCHUNK_P + nt * 8 + 2 * qi;
                fold4(d[0], c0,     V1[0], I1[0], V2[0], I2[0], V3[0], I3[0], V4[0]);
                fold4(d[1], c0 + 1, V1[0], I1[0], V2[0], I2[0], V3[0], I3[0], V4[0]);
                fold4(d[2], c0,     V1[1], I1[1], V2[1], I2[1], V3[1], I3[1], V4[1]);
                fold4(d[3], c0 + 1, V1[1], I1[1], V2[1], I2[1], V3[1], I3[1], V4[1]);
            }
            if (s) ++pc1; else ++pc0;
            __syncthreads();
            if (c + 2 < NCHUNKS && tid == 0) {
                const u32 mb = s ? mb1 : mb0;
                mbar_expect_tx(mb, HI_BLK);
                bulk_g2s(sbase + (u32)s * HI_BLK, g_Bimg + (size_t)(c + 2) * HI_BLK, HI_BLK, mb);
            }
        }

        // quad merge of top-4 lists
        #pragma unroll
        for (int m = 1; m <= 2; m <<= 1) {
            #pragma unroll
            for (int q = 0; q < 2; ++q) {
                float ov1 = __shfl_xor_sync(0xffffffffu, V1[q], m);
                int   oi1 = __shfl_xor_sync(0xffffffffu, I1[q], m);
                float ov2 = __shfl_xor_sync(0xffffffffu, V2[q], m);
                int   oi2 = __shfl_xor_sync(0xffffffffu, I2[q], m);
                float ov3 = __shfl_xor_sync(0xffffffffu, V3[q], m);
                int   oi3 = __shfl_xor_sync(0xffffffffu, I3[q], m);
                float ov4 = __shfl_xor_sync(0xffffffffu, V4[q], m);
                fold4(ov1, oi1, V1[q], I1[q], V2[q], I2[q], V3[q], I3[q], V4[q]);
                fold4(ov2, oi2, V1[q], I1[q], V2[q], I2[q], V3[q], I3[q], V4[q]);
                fold4(ov3, oi3, V1[q], I1[q], V2[q], I2[q], V3[q], I3[q], V4[q]);
                V4[q] = fmaxf(V4[q], ov4);
            }
        }

        if (qi == 0) {
            #pragma unroll
            for (int q = 0; q < 2; ++q) {
                const int rl = wid * 16 + q * 8 + g;
                const int ok = (V1[q] - V4[q] > C4_CERT * sqrtf(nrm2[q])) ? 1 : 0;
                cCand[rl] = make_int4(I1[q], I2[q], I3[q], ok);
            }
        }
        __syncthreads();

        // ---- inline exact resolution: warp w handles tile rows [w*16, w*16+16) ----
        for (int rr = wid * 16; rr < wid * 16 + 16; ++rr) {
            const int row = rowIdx[rr];
            if (row < 0) continue;
            const int4 cd = cCand[rr];
            if (!cd.w) {
                if (lane == 0) { int pos = atomicAdd(&g_nB, 1); g_listB[pos] = row; }
                continue;
            }
            const float4 ef = ((const float4*)(emb + (size_t)row * DIM))[lane];
            float4 pa = p4[cd.x * 32 + lane];
            float4 pb = p4[cd.y * 32 + lane];
            float4 pc = p4[cd.z * 32 + lane];
            float d1 = fmaf(ef.x, pa.x, fmaf(ef.y, pa.y, fmaf(ef.z, pa.z, ef.w * pa.w)));
            float d2 = fmaf(ef.x, pb.x, fmaf(ef.y, pb.y, fmaf(ef.z, pb.z, ef.w * pb.w)));
            float d3 = fmaf(ef.x, pc.x, fmaf(ef.y, pc.y, fmaf(ef.z, pc.z, ef.w * pc.w)));
            #pragma unroll
            for (int m = 16; m; m >>= 1) {
                d1 += __shfl_xor_sync(0xffffffffu, d1, m);
                d2 += __shfl_xor_sync(0xffffffffu, d2, m);
                d3 += __shfl_xor_sync(0xffffffffu, d3, m);
            }
            float bv = d1; int bi = cd.x;
            if (d2 > bv || (d2 == bv && cd.y < bi)) { bv = d2; bi = cd.y; }
            if (d3 > bv || (d3 == bv && cd.z < bi)) { bv = d3; bi = cd.z; }
            if (lane == 0) atomicAdd(&g_counts[bi], 1.0f);
            red4(&g_sums[bi * DIM + lane * 4], ef);
        }
        __syncthreads();   // rowIdx/cCand reuse next tile
    }
}

// ---------------------------------------------------------------------------
// RefineB: warp-per-row full exact fp32 scan (4-way interleaved) + scatter.
__global__ void __launch_bounds__(256, 2)
refineB_kernel(const float* __restrict__ emb) {
    const int w    = blockIdx.x * 8 + (threadIdx.x >> 5);
    const int lane = threadIdx.x & 31;
    const int W    = gridDim.x * 8;
    const int nB = *(volatile int*)&g_nB;
    const float4* p4 = (const float4*)g_proto_n;

    for (int i = w; i < nB; i += W) {
        int row = g_listB[i];
        const float4 ef = ((const float4*)(emb + (size_t)row * DIM))[lane];
        float bv = -3.4e38f; int bi = 0;
        for (int k = 0; k < KCL; k += 4) {
            float d[4];
            #pragma unroll
            for (int u = 0; u < 4; ++u) {
                float4 pf = p4[(k + u) * 32 + lane];
                d[u] = fmaf(ef.x, pf.x, fmaf(ef.y, pf.y, fmaf(ef.z, pf.z, ef.w * pf.w)));
            }
            #pragma unroll
            for (int m = 16; m; m >>= 1) {
                #pragma unroll
                for (int u = 0; u < 4; ++u)
                    d[u] += __shfl_xor_sync(0xffffffffu, d[u], m);
            }
            #pragma unroll
            for (int u = 0; u < 4; ++u)
                if (d[u] > bv) { bv = d[u]; bi = k + u; }   // ascending k = first-max
        }
        if (lane == 0) atomicAdd(&g_counts[bi], 1.0f);
        red4(&g_sums[bi * DIM + lane * 4], ef);
    }
}

// ---------------------------------------------------------------------------
__global__ void finalize_kernel(const float* __restrict__ proto,
                                float* __restrict__ out) {
    int i = blockIdx.x * blockDim.x + threadIdx.x;
    int k = i >> 7;
    float c = g_counts[k];
    float p = proto[i];
    float m = g_sums[i] / fmaxf(c, 1.0f);
    out[i] = (c > 0.0f) ? (0.9f * p + 0.1f * m) : p;
}

// ---------------------------------------------------------------------------
extern "C" void kernel_launch(void* const* d_in, const int* in_sizes, int n_in,
                              void* d_out, int out_size) {
    const float* emb   = (const float*)d_in[0];
    const float* proto = (const float*)d_in[1];
    float* out = (float*)d_out;

    cudaFuncSetAttribute(pass1_kernel,
                         cudaFuncAttributeMaxDynamicSharedMemorySize, P1_SMEM);
    cudaFuncSetAttribute(refineA_kernel,
                         cudaFuncAttributeMaxDynamicSharedMemorySize, RA_SMEM);

    prep_kernel<<<KCL, DIM>>>(proto);
    pass1_kernel<<<BROWS / M_CTA, 256, P1_SMEM>>>(emb);
    refineA_kernel<<<148, 256, RA_SMEM>>>(emb);
    refineB_kernel<<<592, 256>>>(emb);
    finalize_kernel<<<(KCL * DIM) / 256, 256>>>(proto, out);
}